// round 3
// baseline (speedup 1.0000x reference)
#include <cuda_runtime.h>
#include <cuda_bf16.h>

#define M_NODES 50000
#define DFEAT   128
#define N_EDGE  800000
#define EPW     128   // edges per warp in SpMM

// scratch for support = X @ W  (25.6 MB, static device global — no allocs)
__device__ float g_support[(size_t)M_NODES * DFEAT];

// ---------------------------------------------------------------------------
// Kernel 1: out[n, :] = bias[:]   (out is poisoned by harness)
// ---------------------------------------------------------------------------
__global__ __launch_bounds__(256) void init_out_kernel(const float* __restrict__ bias,
                                                       float* __restrict__ out) {
    long long i = (long long)blockIdx.x * blockDim.x + threadIdx.x;  // float4 index
    const long long total4 = (long long)M_NODES * (DFEAT / 4);
    if (i < total4) {
        int c4 = (int)(i & 31);  // 128/4 = 32 float4 per row
        float4 b = ((const float4*)bias)[c4];
        ((float4*)out)[i] = b;
    }
}

// ---------------------------------------------------------------------------
// Kernel 2: SGEMM  g_support = X @ W    (M=50000, N=K=128)
// 128x128 block tile, BK=8, 256 threads, 8x8 microtile per thread.
// Global->register prefetch double-buffering hides LDG latency behind FFMAs.
// ---------------------------------------------------------------------------
__global__ __launch_bounds__(256) void gemm_kernel(const float* __restrict__ A,
                                                   const float* __restrict__ B) {
    __shared__ float As[8][128];   // transposed A tile
    __shared__ float Bs[8][128];

    const int tid = threadIdx.x;
    const int block_row = blockIdx.x * 128;

    const int tx = tid & 15;        // 0..15 -> 8 cols each
    const int ty = tid >> 4;        // 0..15 -> 8 rows each

    // A-tile load mapping: 128 rows x 8 cols = 256 float4 (one per thread)
    const int a_row  = tid >> 1;          // 0..127
    const int a_col4 = (tid & 1) * 4;     // 0 or 4
    // B-tile load mapping: 8 rows x 128 cols = 256 float4 (one per thread)
    const int b_row  = tid >> 5;          // 0..7
    const int b_col4 = (tid & 31) * 4;

    int g_arow = block_row + a_row;
    if (g_arow >= M_NODES) g_arow = M_NODES - 1;   // clamp; output store is guarded
    const float* Aptr = A + (long long)g_arow * DFEAT;

    float acc[8][8];
#pragma unroll
    for (int i = 0; i < 8; i++)
#pragma unroll
        for (int j = 0; j < 8; j++) acc[i][j] = 0.0f;

    // prefetch k0 = 0 tile into registers
    float4 av = *(const float4*)(Aptr + a_col4);
    float4 bv = *(const float4*)(B + (long long)b_row * DFEAT + b_col4);

    for (int k0 = 0; k0 < DFEAT; k0 += 8) {
        // stage current tile to smem
        As[a_col4 + 0][a_row] = av.x;
        As[a_col4 + 1][a_row] = av.y;
        As[a_col4 + 2][a_row] = av.z;
        As[a_col4 + 3][a_row] = av.w;
        *(float4*)&Bs[b_row][b_col4] = bv;
        __syncthreads();

        // prefetch NEXT tile into registers (overlaps with FFMA block below)
        int kn = k0 + 8;
        if (kn < DFEAT) {
            av = *(const float4*)(Aptr + kn + a_col4);
            bv = *(const float4*)(B + (long long)(kn + b_row) * DFEAT + b_col4);
        }

#pragma unroll
        for (int kk = 0; kk < 8; kk++) {
            float a[8], b[8];
#pragma unroll
            for (int i = 0; i < 8; i++) a[i] = As[kk][ty * 8 + i];
#pragma unroll
            for (int j = 0; j < 8; j++) b[j] = Bs[kk][tx * 8 + j];
#pragma unroll
            for (int i = 0; i < 8; i++)
#pragma unroll
                for (int j = 0; j < 8; j++) acc[i][j] = fmaf(a[i], b[j], acc[i][j]);
        }
        __syncthreads();
    }

    // write 8x8 microtile (guard rows for the 50000 % 128 tail)
#pragma unroll
    for (int i = 0; i < 8; i++) {
        int row = block_row + ty * 8 + i;
        if (row < M_NODES) {
            float* dst = g_support + (long long)row * DFEAT + tx * 8;
            float4 v0 = make_float4(acc[i][0], acc[i][1], acc[i][2], acc[i][3]);
            float4 v1 = make_float4(acc[i][4], acc[i][5], acc[i][6], acc[i][7]);
            *(float4*)(dst + 0) = v0;
            *(float4*)(dst + 4) = v1;
        }
    }
}

// ---------------------------------------------------------------------------
// Kernel 3: SpMM scatter.  adj_dst is SORTED, so each warp accumulates runs of
// equal dst in registers and flushes with atomicAdd only at run boundaries
// (and once at chunk end, covering cross-warp shared dst).
// Warp layout: lane l owns columns [4l, 4l+4) as a float4.
// Indices are int32 (JAX default x64-disabled downcasts int64 -> int32).
// ---------------------------------------------------------------------------
__global__ __launch_bounds__(256) void spmm_kernel(const int* __restrict__ src,
                                                   const int* __restrict__ dst,
                                                   const float* __restrict__ val,
                                                   float* __restrict__ out) {
    const int gw   = (int)(((long long)blockIdx.x * blockDim.x + threadIdx.x) >> 5);
    const int lane = threadIdx.x & 31;

    int e0 = gw * EPW;
    if (e0 >= N_EDGE) return;
    int e1 = e0 + EPW;
    if (e1 > N_EDGE) e1 = N_EDGE;

    const float4* sup = (const float4*)g_support;

    float4 acc = make_float4(0.f, 0.f, 0.f, 0.f);
    int cur = dst[e0];

    for (int e = e0; e < e1; ++e) {
        int d = dst[e];                       // warp-uniform broadcast
        if (d != cur) {
            float* o = out + (long long)cur * DFEAT + lane * 4;
            atomicAdd(o + 0, acc.x);
            atomicAdd(o + 1, acc.y);
            atomicAdd(o + 2, acc.z);
            atomicAdd(o + 3, acc.w);
            acc = make_float4(0.f, 0.f, 0.f, 0.f);
            cur = d;
        }
        float v = val[e];                     // warp-uniform
        int   s = src[e];                     // warp-uniform
        float4 sv = sup[(long long)s * (DFEAT / 4) + lane];  // 512B coalesced gather (L2-hot)
        acc.x = fmaf(v, sv.x, acc.x);
        acc.y = fmaf(v, sv.y, acc.y);
        acc.z = fmaf(v, sv.z, acc.z);
        acc.w = fmaf(v, sv.w, acc.w);
    }
    float* o = out + (long long)cur * DFEAT + lane * 4;
    atomicAdd(o + 0, acc.x);
    atomicAdd(o + 1, acc.y);
    atomicAdd(o + 2, acc.z);
    atomicAdd(o + 3, acc.w);
}

// ---------------------------------------------------------------------------
// inputs (metadata order): x[f32 50000*128], adj_src[i32 800000],
//   adj_dst[i32 800000], adj_val[f32 800000], weight[f32 128*128], bias[f32 128]
// output: f32 50000*128
// ---------------------------------------------------------------------------
extern "C" void kernel_launch(void* const* d_in, const int* in_sizes, int n_in,
                              void* d_out, int out_size) {
    const float* x       = (const float*)d_in[0];
    const int*   adj_src = (const int*)d_in[1];
    const int*   adj_dst = (const int*)d_in[2];
    const float* adj_val = (const float*)d_in[3];
    const float* weight  = (const float*)d_in[4];
    const float* bias    = (const float*)d_in[5];
    float*       out     = (float*)d_out;

    // 1) out = bias (broadcast)
    {
        long long total4 = (long long)M_NODES * (DFEAT / 4);   // 1.6M
        int grid = (int)((total4 + 255) / 256);
        init_out_kernel<<<grid, 256>>>(bias, out);
    }
    // 2) support = X @ W
    {
        int grid = (M_NODES + 127) / 128;   // 391
        gemm_kernel<<<grid, 256>>>(x, weight);
    }
    // 3) out += A_sp @ support
    {
        int nwarps  = (N_EDGE + EPW - 1) / EPW;       // 6250
        int threads = 256;
        int grid    = (nwarps * 32 + threads - 1) / threads;  // 782
        spmm_kernel<<<grid, threads>>>(adj_src, adj_dst, adj_val, out);
    }
}